// round 9
// baseline (speedup 1.0000x reference)
#include <cuda_runtime.h>
#include <cuda_bf16.h>
#include <math.h>

#define UNITS   256
#define FT_DIM  128
#define BATCH   32
#define TSTEPS  2048
#define EPSILON 0.01f
#define GAMMA   0.01f

#define CHUNK_T  64                    // timesteps per GEMM row-tile
#define NCHUNK   (TSTEPS / CHUNK_T)    // 32
#define NCOLT    (UNITS / 64)          // 4 column tiles
#define GEMM_CTAS (BATCH * NCHUNK * NCOLT)   // 4096

// ---------------------------------------------------------------------------
// Device scratch (allocation-free contract: __device__ globals)
// ---------------------------------------------------------------------------
__device__ unsigned g_Mpack[UNITS * (UNITS / 2)];          // bf16x2 off-diag M
__device__ float g_h[(size_t)BATCH * TSTEPS * UNITS];      // h = x@V + bias
__device__ int g_cnt[BATCH * NCHUNK];                      // chunk-ready counters

// ---------------------------------------------------------------------------
// Helpers
// ---------------------------------------------------------------------------
typedef unsigned long long u64_t;

__device__ __forceinline__ __nv_bfloat162 u2b(unsigned x) {
    return *reinterpret_cast<__nv_bfloat162*>(&x);
}
__device__ __forceinline__ void ffma2(u64_t& d, u64_t a, u64_t b) {
    asm("fma.rn.f32x2 %0, %1, %2, %0;" : "+l"(d) : "l"(a), "l"(b));
}
__device__ __forceinline__ u64_t pack2(float lo, float hi) {
    u64_t r; asm("mov.b64 %0, {%1, %2};" : "=l"(r) : "f"(lo), "f"(hi)); return r;
}
__device__ __forceinline__ float2 unpack2(u64_t v) {
    float2 f; asm("mov.b64 {%0, %1}, %2;" : "=f"(f.x), "=f"(f.y) : "l"(v)); return f;
}
__device__ __forceinline__ int ld_acquire(const int* p) {
    int v; asm volatile("ld.acquire.gpu.s32 %0, [%1];" : "=r"(v) : "l"(p)); return v;
}

// Branch-free tanh: 7th-order Pade; rel err < 1e-9 for |z| <= ~1 (here <=~0.8).
// Runs OFF the critical path (overlapped with the HFMA2 dot stream).
__device__ __forceinline__ float tanh_pade(float z) {
    float t = z * z;
    float n = fmaf(fmaf(t + 378.0f, t, 17325.0f), t, 135135.0f);
    float d = fmaf(fmaf(fmaf(28.0f, t, 3150.0f), t, 62370.0f), t, 135135.0f);
    return z * __fdividef(n, d);
}

// ---------------------------------------------------------------------------
// Kernel 1: build packed bf16 M = W - W^T (diag -> 0); zero chunk counters.
// ---------------------------------------------------------------------------
__global__ void prep_M_kernel(const float* __restrict__ W) {
    int id = blockIdx.x * blockDim.x + threadIdx.x;      // 0 .. 32767
    if (id < BATCH * NCHUNK) g_cnt[id] = 0;              // reset per replay
    int u = id >> 7;
    int i = id & 127;
    int k0 = 2 * i;
    int k1 = 2 * i + 1;
    float m0 = (k0 == u) ? 0.0f : (W[k0 * UNITS + u] - W[u * UNITS + k0]);
    float m1 = (k1 == u) ? 0.0f : (W[k1 * UNITS + u] - W[u * UNITS + k1]);
    __nv_bfloat162 p = __floats2bfloat162_rn(m0, m1);
    g_Mpack[id] = *reinterpret_cast<unsigned*>(&p);
}

// ---------------------------------------------------------------------------
// Fused kernel: bid 0..31 = scan CTAs (one per batch, start immediately),
//               bid 32..  = GEMM tile CTAs (chunk-major: early timesteps first).
// ---------------------------------------------------------------------------
#define BM 64
#define BN 64
#define BK 32

__global__ void __launch_bounds__(256, 1) fused_kernel(
    const float* __restrict__ x,
    const float* __restrict__ V,
    const float* __restrict__ bias,
    const float* __restrict__ x0,
    float* __restrict__ out)
{
    const int tid = threadIdx.x;

    if (blockIdx.x >= BATCH) {
        // =================== GEMM producer path ===================
        __shared__ float As[BK][BM + 2];
        __shared__ float Bs[BK][BN];

        int bid = blockIdx.x - BATCH;        // 0..4095
        int chunk = bid >> 7;                // time chunk (ascending)
        int rem = bid & 127;
        int b = rem >> 2;                    // batch
        int colTile = rem & 3;
        const int rowBase = b * TSTEPS + chunk * CHUNK_T;
        const int colBase = colTile * BN;

        const int ty = tid >> 4;
        const int tx = tid & 15;

        u64_t acc2[2][4];
#pragma unroll
        for (int p = 0; p < 2; p++)
#pragma unroll
            for (int j = 0; j < 4; j++) acc2[p][j] = 0ULL;

        for (int k0 = 0; k0 < FT_DIM; k0 += BK) {
#pragma unroll
            for (int i = 0; i < 8; i++) {
                int idx = tid + i * 256;
                int m = idx >> 5;
                int k = idx & 31;
                As[k][m] = __ldg(&x[(size_t)(rowBase + m) * FT_DIM + k0 + k]);
            }
#pragma unroll
            for (int i = 0; i < 8; i++) {
                int idx = tid + i * 256;
                int k = idx >> 6;
                int n = idx & 63;
                Bs[k][n] = __ldg(&V[(size_t)(k0 + k) * UNITS + colBase + n]);
            }
            __syncthreads();

#pragma unroll
            for (int k = 0; k < BK; k++) {
                u64_t A0 = *reinterpret_cast<const u64_t*>(&As[k][ty * 4 + 0]);
                u64_t A1 = *reinterpret_cast<const u64_t*>(&As[k][ty * 4 + 2]);
                float4 bv = *reinterpret_cast<const float4*>(&Bs[k][tx * 4]);
                u64_t B0 = pack2(bv.x, bv.x);
                u64_t B1 = pack2(bv.y, bv.y);
                u64_t B2 = pack2(bv.z, bv.z);
                u64_t B3 = pack2(bv.w, bv.w);
                ffma2(acc2[0][0], A0, B0);
                ffma2(acc2[0][1], A0, B1);
                ffma2(acc2[0][2], A0, B2);
                ffma2(acc2[0][3], A0, B3);
                ffma2(acc2[1][0], A1, B0);
                ffma2(acc2[1][1], A1, B1);
                ffma2(acc2[1][2], A1, B2);
                ffma2(acc2[1][3], A1, B3);
            }
            __syncthreads();
        }

        float b0 = bias[colBase + tx * 4 + 0];
        float b1 = bias[colBase + tx * 4 + 1];
        float b2 = bias[colBase + tx * 4 + 2];
        float b3 = bias[colBase + tx * 4 + 3];
#pragma unroll
        for (int p = 0; p < 2; p++) {
            float2 c0 = unpack2(acc2[p][0]);
            float2 c1 = unpack2(acc2[p][1]);
            float2 c2 = unpack2(acc2[p][2]);
            float2 c3 = unpack2(acc2[p][3]);
            size_t r0 = (size_t)(rowBase + ty * 4 + 2 * p);
            float4 v;
            v.x = c0.x + b0; v.y = c1.x + b1; v.z = c2.x + b2; v.w = c3.x + b3;
            *reinterpret_cast<float4*>(&g_h[r0 * UNITS + colBase + tx * 4]) = v;
            v.x = c0.y + b0; v.y = c1.y + b1; v.z = c2.y + b2; v.w = c3.y + b3;
            *reinterpret_cast<float4*>(&g_h[(r0 + 1) * UNITS + colBase + tx * 4]) = v;
        }

        __threadfence();
        __syncthreads();
        if (tid == 0) atomicAdd(&g_cnt[b * NCHUNK + chunk], 1);
        return;
    }

    // =================== Scan consumer path ===================
    __shared__ __align__(16) unsigned sbuf[2][UNITS / 2];

    const int u = tid;
    const int b = blockIdx.x;

    // Load M column u into registers (one-time, vectorized)
    unsigned mreg[128];
    {
        const uint4* mp = reinterpret_cast<const uint4*>(g_Mpack + u * 128);
#pragma unroll
        for (int i = 0; i < 32; i++) {
            uint4 v = mp[i];
            mreg[4 * i + 0] = v.x;
            mreg[4 * i + 1] = v.y;
            mreg[4 * i + 2] = v.z;
            mreg[4 * i + 3] = v.w;
        }
    }

    float s = x0[u];
    reinterpret_cast<__nv_bfloat16*>(sbuf[0])[u] = __float2bfloat16(s);

    // Wait for chunk 0 of this batch (4 column tiles)
    if (u == 0) {
        while (ld_acquire(&g_cnt[b * NCHUNK + 0]) < NCOLT) { }
    }
    __syncthreads();

    const float* hb = g_h + (size_t)b * TSTEPS * UNITS + u;
    float* ob = out + (size_t)b * TSTEPS * UNITS + u;

    float h0 = hb[0];
    float h1 = hb[UNITS];

    int cur = 0;
    int t = 0;
    for (int c = 0; c < NCHUNK; c++) {
        if (c + 1 < NCHUNK) {
            if (u == 0) {
                while (ld_acquire(&g_cnt[b * NCHUNK + c + 1]) < NCOLT) { }
            }
            __syncthreads();
        }

#pragma unroll 1
        for (int i = 0; i < CHUNK_T; i++, t++) {
            // ------- step top: everything derivable from zbase (no dot) -------
            // z = zbase + d, d = M_off . s_vec (tiny, ~1e-4).
            // First-order: tanh(z) ~= T + d*(1-T^2), T = tanh(zbase).
            float zbase = fmaf(-GAMMA, s, h0);
            h0 = h1;
            if (t + 2 < TSTEPS) h1 = hb[(size_t)(t + 2) * UNITS];

            float T = tanh_pade(zbase);              // off critical path (MUFU)
            float s_mid = fmaf(EPSILON, T, s);       // state sans correction
            float epsTp = EPSILON * fmaf(-T, T, 1.0f);

            // Predictive publish for step t+1: correction (eps*T'*d <= 1e-6)
            // is far below bf16 rounding of the published value. This moves
            // cvt+STS off the inter-step critical path.
            reinterpret_cast<__nv_bfloat16*>(sbuf[cur ^ 1])[u] = __float2bfloat16(s_mid);

            // ------------------ dot stream: 128 HFMA2 ------------------
            __nv_bfloat162 a0 = __float2bfloat162_rn(0.0f);
            __nv_bfloat162 a1 = a0, a2 = a0, a3 = a0;

            const uint4* sv = reinterpret_cast<const uint4*>(sbuf[cur]);
#pragma unroll
            for (int j = 0; j < 32; j++) {
                uint4 v = sv[j];   // uniform-address LDS.128: broadcast
                a0 = __hfma2(u2b(mreg[4 * j + 0]), u2b(v.x), a0);
                a1 = __hfma2(u2b(mreg[4 * j + 1]), u2b(v.y), a1);
                a2 = __hfma2(u2b(mreg[4 * j + 2]), u2b(v.z), a2);
                a3 = __hfma2(u2b(mreg[4 * j + 3]), u2b(v.w), a3);
            }

            // ---- short tail: combine + 1 FFMA, then barrier ----
            __nv_bfloat162 acc = __hadd2(__hadd2(a0, a1), __hadd2(a2, a3));
            float2 df = __bfloat1622float2(acc);
            float d = df.x + df.y;

            s = fmaf(epsTp, d, s_mid);               // full corrected fp32 state

            ob[(size_t)t * UNITS] = s;               // off-path coalesced STG
            cur ^= 1;
            __syncthreads();
        }
    }
}

// ---------------------------------------------------------------------------
// Launch: inputs per metadata order: x, V, W, bias, x0
// ---------------------------------------------------------------------------
extern "C" void kernel_launch(void* const* d_in, const int* in_sizes, int n_in,
                              void* d_out, int out_size)
{
    const float* x    = (const float*)d_in[0];   // [32, 2048, 128]
    const float* V    = (const float*)d_in[1];   // [128, 256]
    const float* W    = (const float*)d_in[2];   // [256, 256]
    const float* bias = (const float*)d_in[3];   // [256]
    const float* x0   = (const float*)d_in[4];   // [256]
    float* out = (float*)d_out;                  // [32, 2048, 256]

    (void)in_sizes; (void)n_in; (void)out_size;

    prep_M_kernel<<<(UNITS * UNITS / 2) / 256, 256>>>(W);
    fused_kernel<<<BATCH + GEMM_CTAS, 256>>>(x, V, bias, x0, out);
}

// round 10
// speedup vs baseline: 1.3166x; 1.3166x over previous
#include <cuda_runtime.h>
#include <cuda_bf16.h>
#include <math.h>

#define UNITS   256
#define FT_DIM  128
#define BATCH   32
#define TSTEPS  2048
#define EPSILON 0.01f
#define GAMMA   0.01f

#define CHUNK_T  64                    // timesteps per GEMM row-tile
#define NCHUNK   (TSTEPS / CHUNK_T)    // 32
#define NCOLT    (UNITS / 64)          // 4 column tiles
#define GEMM_CTAS (BATCH * NCHUNK * NCOLT)   // 4096

// State quantization: fixed range +-0.5 -> int8 via *254
#define SQ_SCALE 254.0f
#define SQ_INV   (1.0f / 254.0f)

// ---------------------------------------------------------------------------
// Device scratch (allocation-free contract: __device__ globals)
// ---------------------------------------------------------------------------
__device__ unsigned g_Mq[UNITS * (UNITS / 4)];             // int8 M, packed 4/word
__device__ float g_scale[UNITS];                           // colmax/127 * SQ_INV
__device__ float g_h[(size_t)BATCH * TSTEPS * UNITS];      // h = x@V + bias
__device__ int g_cnt[BATCH * NCHUNK];                      // chunk-ready counters

// ---------------------------------------------------------------------------
// Helpers
// ---------------------------------------------------------------------------
typedef unsigned long long u64_t;

__device__ __forceinline__ void ffma2(u64_t& d, u64_t a, u64_t b) {
    asm("fma.rn.f32x2 %0, %1, %2, %0;" : "+l"(d) : "l"(a), "l"(b));
}
__device__ __forceinline__ u64_t pack2(float lo, float hi) {
    u64_t r; asm("mov.b64 %0, {%1, %2};" : "=l"(r) : "f"(lo), "f"(hi)); return r;
}
__device__ __forceinline__ float2 unpack2(u64_t v) {
    float2 f; asm("mov.b64 {%0, %1}, %2;" : "=f"(f.x), "=f"(f.y) : "l"(v)); return f;
}
__device__ __forceinline__ int ld_acquire(const int* p) {
    int v; asm volatile("ld.acquire.gpu.s32 %0, [%1];" : "=r"(v) : "l"(p)); return v;
}

// Branch-free tanh: 7th-order Pade; rel err < 1e-9 for |z| <= ~1 (here <=~0.8).
__device__ __forceinline__ float tanh_pade(float z) {
    float t = z * z;
    float n = fmaf(fmaf(t + 378.0f, t, 17325.0f), t, 135135.0f);
    float d = fmaf(fmaf(fmaf(28.0f, t, 3150.0f), t, 62370.0f), t, 135135.0f);
    return z * __fdividef(n, d);
}

// Quantize a state value to int8 (range +-0.5)
__device__ __forceinline__ char quant_s(float v) {
    float c = fminf(fmaxf(v, -0.5f), 0.5f);
    return (char)__float2int_rn(c * SQ_SCALE);
}

// ---------------------------------------------------------------------------
// Kernel 1: int8-quantize M = W - W^T (diag->0), one CTA per column u.
// Also zeroes the chunk counters (CTAs 0..3).
// ---------------------------------------------------------------------------
__global__ void __launch_bounds__(256) prep_M_kernel(const float* __restrict__ W) {
    __shared__ float s_m[UNITS];
    __shared__ float red[UNITS];
    __shared__ float s_q;

    const int u = blockIdx.x;       // column
    const int k = threadIdx.x;      // row

    int gid = u * 256 + k;
    if (gid < BATCH * NCHUNK) g_cnt[gid] = 0;    // reset per replay

    float m = (k == u) ? 0.0f : (W[k * UNITS + u] - W[u * UNITS + k]);
    s_m[k] = m;
    red[k] = fabsf(m);
    __syncthreads();

#pragma unroll
    for (int off = 128; off > 0; off >>= 1) {
        if (k < off) red[k] = fmaxf(red[k], red[k + off]);
        __syncthreads();
    }
    if (k == 0) {
        float amax = red[0];
        s_q = (amax > 0.0f) ? (127.0f / amax) : 0.0f;
        g_scale[u] = (amax > 0.0f) ? (amax / 127.0f) * SQ_INV : 0.0f;
    }
    __syncthreads();

    if (k < 64) {
        float q = s_q;
        int q0 = __float2int_rn(s_m[4 * k + 0] * q);
        int q1 = __float2int_rn(s_m[4 * k + 1] * q);
        int q2 = __float2int_rn(s_m[4 * k + 2] * q);
        int q3 = __float2int_rn(s_m[4 * k + 3] * q);
        unsigned w = (unsigned)(q0 & 255) | ((unsigned)(q1 & 255) << 8)
                   | ((unsigned)(q2 & 255) << 16) | ((unsigned)(q3 & 255) << 24);
        g_Mq[u * 64 + k] = w;
    }
}

// ---------------------------------------------------------------------------
// Fused kernel (512 threads launched; 256 active — the extra 256 exit at once
// but pad the CTA's register reservation so no two CTAs ever co-reside on an
// SM: scan CTAs keep their SM exclusively).
//   bid 0..31  : scan CTAs (one per batch)
//   bid 32..   : GEMM tile CTAs, chunk-major (early timesteps first)
// ---------------------------------------------------------------------------
#define BM 64
#define BN 64
#define BK 32

__global__ void __launch_bounds__(512, 1) fused_kernel(
    const float* __restrict__ x,
    const float* __restrict__ V,
    const float* __restrict__ bias,
    const float* __restrict__ x0,
    float* __restrict__ out)
{
    const int tid = threadIdx.x;
    if (tid >= 256) return;          // register-padding threads

    if (blockIdx.x >= BATCH) {
        // =================== GEMM producer path ===================
        __shared__ float As[BK][BM + 2];
        __shared__ float Bs[BK][BN];

        int bid = blockIdx.x - BATCH;        // 0..4095
        int chunk = bid >> 7;                // time chunk (ascending)
        int rem = bid & 127;
        int b = rem >> 2;                    // batch
        int colTile = rem & 3;
        const int rowBase = b * TSTEPS + chunk * CHUNK_T;
        const int colBase = colTile * BN;

        const int ty = tid >> 4;
        const int tx = tid & 15;

        u64_t acc2[2][4];
#pragma unroll
        for (int p = 0; p < 2; p++)
#pragma unroll
            for (int j = 0; j < 4; j++) acc2[p][j] = 0ULL;

        for (int k0 = 0; k0 < FT_DIM; k0 += BK) {
#pragma unroll
            for (int i = 0; i < 8; i++) {
                int idx = tid + i * 256;
                int m = idx >> 5;
                int k = idx & 31;
                As[k][m] = __ldg(&x[(size_t)(rowBase + m) * FT_DIM + k0 + k]);
            }
#pragma unroll
            for (int i = 0; i < 8; i++) {
                int idx = tid + i * 256;
                int k = idx >> 6;
                int n = idx & 63;
                Bs[k][n] = __ldg(&V[(size_t)(k0 + k) * UNITS + colBase + n]);
            }
            __syncthreads();

#pragma unroll
            for (int k = 0; k < BK; k++) {
                u64_t A0 = *reinterpret_cast<const u64_t*>(&As[k][ty * 4 + 0]);
                u64_t A1 = *reinterpret_cast<const u64_t*>(&As[k][ty * 4 + 2]);
                float4 bv = *reinterpret_cast<const float4*>(&Bs[k][tx * 4]);
                u64_t B0 = pack2(bv.x, bv.x);
                u64_t B1 = pack2(bv.y, bv.y);
                u64_t B2 = pack2(bv.z, bv.z);
                u64_t B3 = pack2(bv.w, bv.w);
                ffma2(acc2[0][0], A0, B0);
                ffma2(acc2[0][1], A0, B1);
                ffma2(acc2[0][2], A0, B2);
                ffma2(acc2[0][3], A0, B3);
                ffma2(acc2[1][0], A1, B0);
                ffma2(acc2[1][1], A1, B1);
                ffma2(acc2[1][2], A1, B2);
                ffma2(acc2[1][3], A1, B3);
            }
            __syncthreads();
        }

        float b0 = bias[colBase + tx * 4 + 0];
        float b1 = bias[colBase + tx * 4 + 1];
        float b2 = bias[colBase + tx * 4 + 2];
        float b3 = bias[colBase + tx * 4 + 3];
#pragma unroll
        for (int p = 0; p < 2; p++) {
            float2 c0 = unpack2(acc2[p][0]);
            float2 c1 = unpack2(acc2[p][1]);
            float2 c2 = unpack2(acc2[p][2]);
            float2 c3 = unpack2(acc2[p][3]);
            size_t r0 = (size_t)(rowBase + ty * 4 + 2 * p);
            float4 v;
            v.x = c0.x + b0; v.y = c1.x + b1; v.z = c2.x + b2; v.w = c3.x + b3;
            *reinterpret_cast<float4*>(&g_h[r0 * UNITS + colBase + tx * 4]) = v;
            v.x = c0.y + b0; v.y = c1.y + b1; v.z = c2.y + b2; v.w = c3.y + b3;
            *reinterpret_cast<float4*>(&g_h[(r0 + 1) * UNITS + colBase + tx * 4]) = v;
        }

        __threadfence();
        __syncthreads();
        if (tid == 0) atomicAdd(&g_cnt[b * NCHUNK + chunk], 1);
        return;
    }

    // =================== Scan consumer path ===================
    // Double-buffered int8 state (256 bytes per buffer).
    __shared__ __align__(16) unsigned sbuf[2][UNITS / 4];

    const int u = tid;
    const int b = blockIdx.x;

    // Load int8 M column u into 64 words (one-time, vectorized)
    unsigned mq[64];
    {
        const uint4* mp = reinterpret_cast<const uint4*>(g_Mq + u * 64);
#pragma unroll
        for (int i = 0; i < 16; i++) {
            uint4 v = mp[i];
            mq[4 * i + 0] = v.x;
            mq[4 * i + 1] = v.y;
            mq[4 * i + 2] = v.z;
            mq[4 * i + 3] = v.w;
        }
    }
    const float scu = g_scale[u];    // combined dequant scale (M * state)

    float s = x0[u];
    reinterpret_cast<char*>(sbuf[0])[u] = quant_s(s);

    // Wait for chunk 0 of this batch (4 column tiles)
    if (u == 0) {
        while (ld_acquire(&g_cnt[b * NCHUNK + 0]) < NCOLT) { }
    }
    __syncthreads();

    const float* hb = g_h + (size_t)b * TSTEPS * UNITS + u;
    float* ob = out + (size_t)b * TSTEPS * UNITS + u;

    float h0 = hb[0];
    float h1 = hb[UNITS];

    int cur = 0;
    int t = 0;
    for (int c = 0; c < NCHUNK; c++) {
        if (c + 1 < NCHUNK) {
            if (u == 0) {
                while (ld_acquire(&g_cnt[b * NCHUNK + c + 1]) < NCOLT) { }
            }
            __syncthreads();
        }

#pragma unroll 1
        for (int i = 0; i < CHUNK_T; i++, t++) {
            // ------- step top: everything derivable from zbase (no dot) -------
            // z = zbase + d;  tanh(z) ~= T + d*(1-T^2),  |d| ~ 1e-4.
            float zbase = fmaf(-GAMMA, s, h0);
            h0 = h1;
            if (t + 2 < TSTEPS) h1 = hb[(size_t)(t + 2) * UNITS];

            float T = tanh_pade(zbase);              // off critical path
            float s_mid = fmaf(EPSILON, T, s);
            float cc = (EPSILON * fmaf(-T, T, 1.0f)) * scu;  // epsT' * dequant

            // Predictive int8 publish for step t+1 (correction ~1e-6 is far
            // below the int8 quantization step of the published value).
            reinterpret_cast<char*>(sbuf[cur ^ 1])[u] = quant_s(s_mid);

            // ---------- dot stream: 64 DP4A (4 MACs each, exact int32) -------
            int a0 = 0, a1 = 0, a2 = 0, a3 = 0;
            const uint4* sv = reinterpret_cast<const uint4*>(sbuf[cur]);
#pragma unroll
            for (int j = 0; j < 16; j++) {
                uint4 v = sv[j];   // uniform-address LDS.128: broadcast
                a0 = __dp4a((int)mq[4 * j + 0], (int)v.x, a0);
                a1 = __dp4a((int)mq[4 * j + 1], (int)v.y, a1);
                a2 = __dp4a((int)mq[4 * j + 2], (int)v.z, a2);
                a3 = __dp4a((int)mq[4 * j + 3], (int)v.w, a3);
            }

            // ---- short tail: 3 IADD + I2F + 1 FFMA, then barrier ----
            int di = (a0 + a1) + (a2 + a3);
            s = fmaf(cc, (float)di, s_mid);

            ob[(size_t)t * UNITS] = s;               // off-path coalesced STG
            cur ^= 1;
            __syncthreads();
        }
    }
}

// ---------------------------------------------------------------------------
// Launch: inputs per metadata order: x, V, W, bias, x0
// ---------------------------------------------------------------------------
extern "C" void kernel_launch(void* const* d_in, const int* in_sizes, int n_in,
                              void* d_out, int out_size)
{
    const float* x    = (const float*)d_in[0];   // [32, 2048, 128]
    const float* V    = (const float*)d_in[1];   // [128, 256]
    const float* W    = (const float*)d_in[2];   // [256, 256]
    const float* bias = (const float*)d_in[3];   // [256]
    const float* x0   = (const float*)d_in[4];   // [256]
    float* out = (float*)d_out;                  // [32, 2048, 256]

    (void)in_sizes; (void)n_in; (void)out_size;

    // 1) int8-quantize M (one CTA per column) + reset chunk counters
    prep_M_kernel<<<UNITS, 256>>>(W);

    // 2) Fused: scan CTAs (0..31) + chunk-major GEMM CTAs; 512-thread launch
    //    pads each CTA's register reservation to keep 1 CTA/SM everywhere.
    fused_kernel<<<BATCH + GEMM_CTAS, 512>>>(x, V, bias, x0, out);
}